// round 10
// baseline (speedup 1.0000x reference)
#include <cuda_runtime.h>
#include <cstdint>

// Problem constants
#define BB   2
#define TT   2048
#define CCH  1024
#define HH   16
#define HDIM 64
#define NTOK (BB * TT)     // 4096
#define C3   (3 * CCH)     // 3072

// Scratch (allocation-free rule: __device__ globals)
__device__ float  g_qkv[(size_t)NTOK * C3];     // [4096, 3072] fp32
__device__ float  g_att[(size_t)NTOK * CCH];    // [4096, 1024] fp32
__device__ float2 g_x2[(size_t)NTOK * CCH];     // x split hi/lo
__device__ float2 g_att2[(size_t)NTOK * CCH];   // att split hi/lo
__device__ float  g_wqkvTh[(size_t)C3 * CCH];   // Wqkv^T tf32-hi [3072][1024]
__device__ float  g_woTh[(size_t)CCH * CCH];    // Wo^T tf32-hi [1024][1024]

// ---------------------------------------------------------------------------
// helpers
// ---------------------------------------------------------------------------
__device__ __forceinline__ uint32_t smem_u32(const void* p) {
    uint32_t a;
    asm("{ .reg .u64 t; cvta.to.shared.u64 t, %1; cvt.u32.u64 %0, t; }" : "=r"(a) : "l"(p));
    return a;
}

__device__ __forceinline__ void cp_async16(uint32_t saddr, const void* gaddr) {
    asm volatile("cp.async.ca.shared.global [%0], [%1], 16;" :: "r"(saddr), "l"(gaddr) : "memory");
}
#define CP_COMMIT() asm volatile("cp.async.commit_group;" ::: "memory")
#define CP_WAIT(n)  asm volatile("cp.async.wait_group %0;" :: "n"(n) : "memory")

__device__ __forceinline__ void mma_tf32(float* c, const uint32_t* a, const uint32_t* b) {
    asm volatile(
        "mma.sync.aligned.m16n8k8.row.col.f32.tf32.tf32.f32 "
        "{%0,%1,%2,%3}, {%4,%5,%6,%7}, {%8,%9}, {%0,%1,%2,%3};"
        : "+f"(c[0]), "+f"(c[1]), "+f"(c[2]), "+f"(c[3])
        : "r"(a[0]), "r"(a[1]), "r"(a[2]), "r"(a[3]), "r"(b[0]), "r"(b[1]));
}

__device__ __forceinline__ uint32_t f2tf(float x) {
    uint32_t r;
    asm("cvt.rna.tf32.f32 %0, %1;" : "=r"(r) : "f"(x));
    return r;
}
__device__ __forceinline__ void tf32_split(float x, uint32_t& hi, uint32_t& lo) {
    hi = f2tf(x);
    lo = f2tf(x - __uint_as_float(hi));
}
__device__ __forceinline__ void tf32_split_f(float x, float& hi, float& lo) {
    uint32_t h = f2tf(x);
    hi = __uint_as_float(h);
    lo = __uint_as_float(f2tf(x - hi));
}
__device__ __forceinline__ float2 split2(float x) {
    float hi, lo;
    tf32_split_f(x, hi, lo);
    return make_float2(hi, lo);
}

// MUFU-free 2^u for u <= 0. ~2e-6 rel accuracy.
__device__ __forceinline__ float exp2p(float u) {
    u = fmaxf(u, -126.f);
    float z = u + 12582912.f;
    int ki = __float_as_int(z) - 0x4B400000;
    float r = u - (z - 12582912.f);
    float p = 0.00133336f;
    p = fmaf(p, r, 0.00961813f);
    p = fmaf(p, r, 0.05550411f);
    p = fmaf(p, r, 0.24022651f);
    p = fmaf(p, r, 0.69314718f);
    p = fmaf(p, r, 1.0f);
    return __int_as_float(__float_as_int(p) + (ki << 23));
}

// ---------------------------------------------------------------------------
// split pass: fp32 -> float2(hi,lo)
// ---------------------------------------------------------------------------
__global__ void __launch_bounds__(256) split_k(
    const float* __restrict__ in, float2* __restrict__ out, int n)
{
    const int i4 = (blockIdx.x * 256 + threadIdx.x) * 4;
    if (i4 < n) {
        float4 v = *(const float4*)(in + i4);
        out[i4 + 0] = split2(v.x);
        out[i4 + 1] = split2(v.y);
        out[i4 + 2] = split2(v.z);
        out[i4 + 3] = split2(v.w);
    }
}

// ---------------------------------------------------------------------------
// transpose + tf32-round (hi only): out[c][r] = tf32(in[r][c])
// ---------------------------------------------------------------------------
__global__ void __launch_bounds__(256) transpose_round(
    const float* __restrict__ in, float* __restrict__ out, int R, int Cc)
{
    __shared__ float t[32][33];
    const int c0 = blockIdx.x * 32, r0 = blockIdx.y * 32;
    const int x = threadIdx.x, y = threadIdx.y;
#pragma unroll
    for (int i = 0; i < 32; i += 8)
        t[y + i][x] = in[(size_t)(r0 + y + i) * Cc + c0 + x];
    __syncthreads();
#pragma unroll
    for (int i = 0; i < 32; i += 8)
        out[(size_t)(c0 + y + i) * R + r0 + x] = __uint_as_float(f2tf(t[x][y + i]));
}

// ---------------------------------------------------------------------------
// 2-term TF32 GEMM: C[M,N] = A2[M][K] @ Bh[N][K]^T + bias[N]
// A2 = (hi,lo) float2 exact split; Bh = tf32-rounded weights.
// CTA 128x128x16, 256 thr = 8 warps (2m x 4n), 3-stage cp.async pipeline,
// one __syncthreads per iter. Conflict-free pitches (A:20 float2, B:20 float).
// ---------------------------------------------------------------------------
#define GP2 20                               // float2 per A smem row
#define BPF 20                               // float per B smem row
#define ASTG (128 * GP2 * 8)                 // 20480 B
#define BSTG (128 * BPF * 4)                 // 10240 B
#define STG  (ASTG + BSTG)                   // 30720 B
#define SMEM_GEMM (3 * STG)                  // 92160 B

__global__ void __launch_bounds__(256, 2) gemm_mma(
    const float2* __restrict__ A2, const float* __restrict__ Bh,
    const float* __restrict__ bias, float* __restrict__ C,
    int N, int K)
{
    extern __shared__ char smem[];
    const uint32_t sb = smem_u32(smem);

    const int tid = threadIdx.x;
    const int lane = tid & 31;
    const int wid = tid >> 5;
    const int wm = (wid & 1) * 64;
    const int wn = (wid >> 1) * 32;
    const int g = lane >> 2;
    const int t = lane & 3;

    const int row0 = blockIdx.y * 128;
    const int col0 = blockIdx.x * 128;

    const int ldrow = tid >> 1;          // 0..127
    const int lhalf = tid & 1;           // 0/1

    float c[4][4][4];
#pragma unroll
    for (int mf = 0; mf < 4; mf++)
#pragma unroll
        for (int nf = 0; nf < 4; nf++)
#pragma unroll
            for (int i = 0; i < 4; i++) c[mf][nf][i] = 0.f;

    const int niter = K / 16;

    // stage s: A at sb + s*STG, B at sb + s*STG + ASTG
#define LOAD_STAGE(it, s)                                                        \
    {                                                                            \
        const int k0_ = (it) * 16;                                               \
        const uint32_t sa = sb + (s) * STG + (uint32_t)(ldrow * GP2) * 8;        \
        const uint32_t sbm = sb + (s) * STG + ASTG + (uint32_t)(ldrow * BPF) * 4;\
        const float2* ga = A2 + (size_t)(row0 + ldrow) * K + k0_;                \
        const float*  gb = Bh + (size_t)(col0 + ldrow) * K + k0_;                \
        _Pragma("unroll")                                                        \
        for (int ch = 0; ch < 4; ch++)                                           \
            cp_async16(sa + (lhalf * 4 + ch) * 16, ga + (lhalf * 4 + ch) * 2);   \
        _Pragma("unroll")                                                        \
        for (int ch = 0; ch < 2; ch++)                                           \
            cp_async16(sbm + (lhalf * 2 + ch) * 16, gb + (lhalf * 2 + ch) * 4);  \
        CP_COMMIT();                                                             \
    }

    LOAD_STAGE(0, 0);
    LOAD_STAGE(1, 1);
    CP_WAIT(1);
    __syncthreads();

    for (int it = 0; it < niter; it++) {
        const int buf = it % 3;
        const float2* Ab = (const float2*)(smem + buf * STG);
        const float*  Bb = (const float*)(smem + buf * STG + ASTG);

#pragma unroll
        for (int ks = 0; ks < 2; ks++) {
            const int k = ks * 8 + t;
            uint32_t ah[4][4], al[4][4], bh[4][2];
#pragma unroll
            for (int mf = 0; mf < 4; mf++) {
                const int r = (wm + mf * 16 + g) * GP2 + k;
                float2 a0 = Ab[r];
                float2 a1 = Ab[r + 8 * GP2];
                float2 a2 = Ab[r + 4];
                float2 a3 = Ab[r + 8 * GP2 + 4];
                ah[mf][0] = __float_as_uint(a0.x); al[mf][0] = __float_as_uint(a0.y);
                ah[mf][1] = __float_as_uint(a1.x); al[mf][1] = __float_as_uint(a1.y);
                ah[mf][2] = __float_as_uint(a2.x); al[mf][2] = __float_as_uint(a2.y);
                ah[mf][3] = __float_as_uint(a3.x); al[mf][3] = __float_as_uint(a3.y);
            }
#pragma unroll
            for (int nf = 0; nf < 4; nf++) {
                const int r = (wn + nf * 8 + g) * BPF + k;
                bh[nf][0] = __float_as_uint(Bb[r]);
                bh[nf][1] = __float_as_uint(Bb[r + 4]);
            }
#pragma unroll
            for (int mf = 0; mf < 4; mf++)
#pragma unroll
                for (int nf = 0; nf < 4; nf++) {
                    mma_tf32(c[mf][nf], al[mf], bh[nf]);
                    mma_tf32(c[mf][nf], ah[mf], bh[nf]);
                }
        }

        if (it + 2 < niter) {
            LOAD_STAGE(it + 2, (it + 2) % 3);
            CP_WAIT(1);
        } else {
            CP_WAIT(0);
        }
        __syncthreads();
    }
#undef LOAD_STAGE

#pragma unroll
    for (int mf = 0; mf < 4; mf++) {
        const int r0_ = row0 + wm + mf * 16 + g;
#pragma unroll
        for (int nf = 0; nf < 4; nf++) {
            const int cc = col0 + wn + nf * 8 + t * 2;
            const float b0 = bias[cc], b1 = bias[cc + 1];
            float2 lo = make_float2(c[mf][nf][0] + b0, c[mf][nf][1] + b1);
            float2 hi = make_float2(c[mf][nf][2] + b0, c[mf][nf][3] + b1);
            *(float2*)&C[(size_t)r0_ * N + cc]       = lo;
            *(float2*)&C[(size_t)(r0_ + 8) * N + cc] = hi;
        }
    }
}

// ---------------------------------------------------------------------------
// 2-term TF32 flash attention (unchanged from R8 — 333 us measured)
// ---------------------------------------------------------------------------
#define APITCH 68
#define KHI_OFF  0
#define VTHI_OFF 4352
#define VTLO_OFF 8704
#define P_OFF    13056
#define ATT_FLOATS 17408
#define ATT_SMEM (ATT_FLOATS * 4)          // 69632 bytes

__global__ void __launch_bounds__(128, 3) attn_mma(
    const float* __restrict__ qkv, float* __restrict__ out)
{
    extern __shared__ float sm[];
    const int tid = threadIdx.x;
    const int lane = tid & 31;
    const int wid = tid >> 5;
    const int g = lane >> 2;
    const int t = lane & 3;

    const int bh = blockIdx.y;
    const int b = bh >> 4;
    const int h = bh & 15;
    const int qtile = (int)gridDim.x - 1 - (int)blockIdx.x;
    const int q0 = qtile * 64;

    float* PHI = sm + P_OFF + wid * 1088;

    const float QSCALE = 0.125f * 1.44269504f;
    const int grow0 = q0 + wid * 16 + g;
    const int grow1 = grow0 + 8;
    const float* q0p = qkv + (size_t)(b * TT + grow0) * C3 + h * HDIM;
    const float* q1p = q0p + (size_t)8 * C3;

    uint32_t qh[8][4], ql[8][4];
#pragma unroll
    for (int ks = 0; ks < 8; ks++) {
        tf32_split(q0p[ks * 8 + t]     * QSCALE, qh[ks][0], ql[ks][0]);
        tf32_split(q1p[ks * 8 + t]     * QSCALE, qh[ks][1], ql[ks][1]);
        tf32_split(q0p[ks * 8 + t + 4] * QSCALE, qh[ks][2], ql[ks][2]);
        tf32_split(q1p[ks * 8 + t + 4] * QSCALE, qh[ks][3], ql[ks][3]);
    }

    float o[8][4];
#pragma unroll
    for (int nf = 0; nf < 8; nf++)
#pragma unroll
        for (int i = 0; i < 4; i++) o[nf][i] = 0.f;
    float m0 = -1e30f, m1 = -1e30f, l0 = 0.f, l1 = 0.f;

    const int ntiles = qtile + 1;
    const float* kbase0 = qkv + (size_t)b * TT * C3 + CCH + h * HDIM;

    for (int tile = 0; tile < ntiles; tile++) {
        const int kv0 = tile * 64;
        const float* kb = kbase0 + (size_t)kv0 * C3;

        __syncthreads();

#pragma unroll
        for (int i = 0; i < 8; i++) {
            const int idx = tid + i * 128;
            const int r = idx >> 4, c4 = idx & 15;
            float4 kv4 = *(const float4*)(kb + (size_t)r * C3 + c4 * 4);
            float4 kh4;
            kh4.x = __uint_as_float(f2tf(kv4.x));
            kh4.y = __uint_as_float(f2tf(kv4.y));
            kh4.z = __uint_as_float(f2tf(kv4.z));
            kh4.w = __uint_as_float(f2tf(kv4.w));
            *(float4*)&sm[KHI_OFF + r * APITCH + c4 * 4] = kh4;
        }
#pragma unroll
        for (int j = 0; j < 2; j++) {
            const int bb2 = tid + j * 128;
            const int br = (bb2 >> 4) * 4;
            const int bc = (bb2 & 15) * 4;
            const float* vb = kb + CCH;
            float4 v0 = *(const float4*)(vb + (size_t)(br + 0) * C3 + bc);
            float4 v1 = *(const float4*)(vb + (size_t)(br + 1) * C3 + bc);
            float4 v2 = *(const float4*)(vb + (size_t)(br + 2) * C3 + bc);
            float4 v3 = *(const float4*)(vb + (size_t)(br + 3) * C3 + bc);
            float4 rowv[4] = {
                make_float4(v0.x, v1.x, v2.x, v3.x),
                make_float4(v0.y, v1.y, v2.y, v3.y),
                make_float4(v0.z, v1.z, v2.z, v3.z),
                make_float4(v0.w, v1.w, v2.w, v3.w)
            };
#pragma unroll
            for (int d = 0; d < 4; d++) {
                float4 hi4, lo4;
                tf32_split_f(rowv[d].x, hi4.x, lo4.x);
                tf32_split_f(rowv[d].y, hi4.y, lo4.y);
                tf32_split_f(rowv[d].z, hi4.z, lo4.z);
                tf32_split_f(rowv[d].w, hi4.w, lo4.w);
                *(float4*)&sm[VTHI_OFF + (bc + d) * APITCH + br] = hi4;
                *(float4*)&sm[VTLO_OFF + (bc + d) * APITCH + br] = lo4;
            }
        }
        __syncthreads();

        float s[8][4];
#pragma unroll
        for (int nf = 0; nf < 8; nf++) {
#pragma unroll
            for (int i = 0; i < 4; i++) s[nf][i] = 0.f;
            const int krow = (nf * 8 + g) * APITCH;
#pragma unroll
            for (int ks = 0; ks < 8; ks++) {
                uint32_t bh2[2];
                bh2[0] = __float_as_uint(sm[KHI_OFF + krow + ks * 8 + t]);
                bh2[1] = __float_as_uint(sm[KHI_OFF + krow + ks * 8 + t + 4]);
                mma_tf32(s[nf], ql[ks], bh2);
                mma_tf32(s[nf], qh[ks], bh2);
            }
        }

        if (tile == qtile) {
#pragma unroll
            for (int nf = 0; nf < 8; nf++) {
                const int c0 = kv0 + nf * 8 + 2 * t;
                if (c0 > grow0)     s[nf][0] = -1e30f;
                if (c0 + 1 > grow0) s[nf][1] = -1e30f;
                if (c0 > grow1)     s[nf][2] = -1e30f;
                if (c0 + 1 > grow1) s[nf][3] = -1e30f;
            }
        }

        float tm0 = -1e30f, tm1 = -1e30f;
#pragma unroll
        for (int nf = 0; nf < 8; nf++) {
            tm0 = fmaxf(tm0, fmaxf(s[nf][0], s[nf][1]));
            tm1 = fmaxf(tm1, fmaxf(s[nf][2], s[nf][3]));
        }
        tm0 = fmaxf(tm0, __shfl_xor_sync(0xffffffffu, tm0, 1));
        tm0 = fmaxf(tm0, __shfl_xor_sync(0xffffffffu, tm0, 2));
        tm1 = fmaxf(tm1, __shfl_xor_sync(0xffffffffu, tm1, 1));
        tm1 = fmaxf(tm1, __shfl_xor_sync(0xffffffffu, tm1, 2));
        const float mn0 = fmaxf(m0, tm0);
        const float mn1 = fmaxf(m1, tm1);
        const float cr0 = exp2p(m0 - mn0);
        const float cr1 = exp2p(m1 - mn1);
        m0 = mn0; m1 = mn1;
        l0 *= cr0; l1 *= cr1;
#pragma unroll
        for (int nf = 0; nf < 8; nf++) {
            o[nf][0] *= cr0; o[nf][1] *= cr0;
            o[nf][2] *= cr1; o[nf][3] *= cr1;
        }

#pragma unroll
        for (int nf = 0; nf < 8; nf++) {
            const float p0 = exp2p(s[nf][0] - m0);
            const float p1 = exp2p(s[nf][1] - m0);
            const float p2 = exp2p(s[nf][2] - m1);
            const float p3 = exp2p(s[nf][3] - m1);
            l0 += p0 + p1;
            l1 += p2 + p3;
            const int cidx = nf * 8 + 2 * t;
            *(float2*)&PHI[g * APITCH + cidx] =
                make_float2(__uint_as_float(f2tf(p0)), __uint_as_float(f2tf(p1)));
            *(float2*)&PHI[(g + 8) * APITCH + cidx] =
                make_float2(__uint_as_float(f2tf(p2)), __uint_as_float(f2tf(p3)));
        }
        __syncwarp();

#pragma unroll
        for (int ks = 0; ks < 8; ks++) {
            uint32_t pah[4];
            pah[0] = __float_as_uint(PHI[g * APITCH + ks * 8 + t]);
            pah[1] = __float_as_uint(PHI[(g + 8) * APITCH + ks * 8 + t]);
            pah[2] = __float_as_uint(PHI[g * APITCH + ks * 8 + t + 4]);
            pah[3] = __float_as_uint(PHI[(g + 8) * APITCH + ks * 8 + t + 4]);
#pragma unroll
            for (int nf = 0; nf < 8; nf++) {
                const int vrow = (nf * 8 + g) * APITCH;
                uint32_t vh[2], vl[2];
                vh[0] = __float_as_uint(sm[VTHI_OFF + vrow + ks * 8 + t]);
                vh[1] = __float_as_uint(sm[VTHI_OFF + vrow + ks * 8 + t + 4]);
                vl[0] = __float_as_uint(sm[VTLO_OFF + vrow + ks * 8 + t]);
                vl[1] = __float_as_uint(sm[VTLO_OFF + vrow + ks * 8 + t + 4]);
                mma_tf32(o[nf], pah, vl);
                mma_tf32(o[nf], pah, vh);
            }
        }
        __syncwarp();
    }

    l0 += __shfl_xor_sync(0xffffffffu, l0, 1);
    l0 += __shfl_xor_sync(0xffffffffu, l0, 2);
    l1 += __shfl_xor_sync(0xffffffffu, l1, 1);
    l1 += __shfl_xor_sync(0xffffffffu, l1, 2);
    const float inv0 = 1.f / l0;
    const float inv1 = 1.f / l1;

    float* op0 = out + (size_t)(b * TT + grow0) * CCH + h * HDIM;
    float* op1 = out + (size_t)(b * TT + grow1) * CCH + h * HDIM;
#pragma unroll
    for (int nf = 0; nf < 8; nf++) {
        const int cidx = nf * 8 + 2 * t;
        *(float2*)&op0[cidx] = make_float2(o[nf][0] * inv0, o[nf][1] * inv0);
        *(float2*)&op1[cidx] = make_float2(o[nf][2] * inv1, o[nf][3] * inv1);
    }
}

// ---------------------------------------------------------------------------
extern "C" void kernel_launch(void* const* d_in, const int* in_sizes, int n_in,
                              void* d_out, int out_size)
{
    (void)in_sizes; (void)n_in; (void)out_size;
    const float* x    = (const float*)d_in[0];
    const float* Wqkv = (const float*)d_in[1];
    const float* bqkv = (const float*)d_in[2];
    const float* Wo   = (const float*)d_in[3];
    const float* bo   = (const float*)d_in[4];
    float* out = (float*)d_out;

    float  *qkvbuf, *attbuf, *wqkvTh, *woTh;
    float2 *x2, *att2;
    cudaGetSymbolAddress((void**)&qkvbuf, g_qkv);
    cudaGetSymbolAddress((void**)&attbuf, g_att);
    cudaGetSymbolAddress((void**)&x2,     g_x2);
    cudaGetSymbolAddress((void**)&att2,   g_att2);
    cudaGetSymbolAddress((void**)&wqkvTh, g_wqkvTh);
    cudaGetSymbolAddress((void**)&woTh,   g_woTh);

    static int smem_set = 0;
    if (!smem_set) {
        cudaFuncSetAttribute(gemm_mma, cudaFuncAttributeMaxDynamicSharedMemorySize, SMEM_GEMM);
        cudaFuncSetAttribute(attn_mma, cudaFuncAttributeMaxDynamicSharedMemorySize, ATT_SMEM);
        smem_set = 1;
    }

    // 0) prep: transpose+round weights (hi-only), split x
    transpose_round<<<dim3(C3 / 32, CCH / 32), dim3(32, 8)>>>(Wqkv, wqkvTh, CCH, C3);
    transpose_round<<<dim3(CCH / 32, CCH / 32), dim3(32, 8)>>>(Wo, woTh, CCH, CCH);
    split_k<<<(NTOK * CCH / 4 + 255) / 256, 256>>>(x, x2, NTOK * CCH);

    // 1) QKV projection (2-term TF32)
    gemm_mma<<<dim3(C3 / 128, NTOK / 128), 256, SMEM_GEMM>>>(x2, wqkvTh, bqkv, qkvbuf, C3, CCH);

    // 2) causal flash attention (2-term TF32)
    attn_mma<<<dim3(TT / 64, BB * HH), 128, ATT_SMEM>>>(qkvbuf, attbuf);

    // 3) split attention output, then output projection (2-term TF32)
    split_k<<<(NTOK * CCH / 4 + 255) / 256, 256>>>(attbuf, att2, NTOK * CCH);
    gemm_mma<<<dim3(CCH / 128, NTOK / 128), 256, SMEM_GEMM>>>(att2, woTh, bo, out, CCH, CCH);
}

// round 11
// speedup vs baseline: 1.5047x; 1.5047x over previous
#include <cuda_runtime.h>
#include <cuda_bf16.h>
#include <cstdint>

// Problem constants
#define BB   2
#define TT   2048
#define CCH  1024
#define HH   16
#define HDIM 64
#define NTOK (BB * TT)     // 4096
#define C3   (3 * CCH)     // 3072

// Scratch (allocation-free rule: __device__ globals)
__device__ float g_qkv[(size_t)NTOK * C3];    // [4096, 3072] fp32
__device__ float g_att[(size_t)NTOK * CCH];   // [4096, 1024] fp32
__device__ __nv_bfloat16 g_xh[(size_t)NTOK * CCH];
__device__ __nv_bfloat16 g_xl[(size_t)NTOK * CCH];
__device__ __nv_bfloat16 g_ath[(size_t)NTOK * CCH];
__device__ __nv_bfloat16 g_atl[(size_t)NTOK * CCH];
__device__ __nv_bfloat16 g_wqh[(size_t)C3 * CCH];   // Wqkv^T hi [3072][1024]
__device__ __nv_bfloat16 g_wql[(size_t)C3 * CCH];
__device__ __nv_bfloat16 g_woh[(size_t)CCH * CCH];  // Wo^T hi
__device__ __nv_bfloat16 g_wol[(size_t)CCH * CCH];

// ---------------------------------------------------------------------------
// helpers
// ---------------------------------------------------------------------------
__device__ __forceinline__ uint32_t smem_u32(const void* p) {
    uint32_t a;
    asm("{ .reg .u64 t; cvta.to.shared.u64 t, %1; cvt.u32.u64 %0, t; }" : "=r"(a) : "l"(p));
    return a;
}
__device__ __forceinline__ void cp_async16(uint32_t saddr, const void* gaddr) {
    asm volatile("cp.async.ca.shared.global [%0], [%1], 16;" :: "r"(saddr), "l"(gaddr) : "memory");
}
#define CP_COMMIT() asm volatile("cp.async.commit_group;" ::: "memory")
#define CP_WAIT(n)  asm volatile("cp.async.wait_group %0;" :: "n"(n) : "memory")

// bf16 m16n8k16 mma, fp32 accumulate
__device__ __forceinline__ void mma_bf(float* c, const uint32_t* a, const uint32_t* b) {
    asm volatile(
        "mma.sync.aligned.m16n8k16.row.col.f32.bf16.bf16.f32 "
        "{%0,%1,%2,%3}, {%4,%5,%6,%7}, {%8,%9}, {%0,%1,%2,%3};"
        : "+f"(c[0]), "+f"(c[1]), "+f"(c[2]), "+f"(c[3])
        : "r"(a[0]), "r"(a[1]), "r"(a[2]), "r"(a[3]), "r"(b[0]), "r"(b[1]));
}

// pack two floats -> bf16x2 (a in LOW half, b in HIGH half), rn rounding
__device__ __forceinline__ uint32_t pack2(float a, float b) {
    uint32_t r;
    asm("cvt.rn.bf16x2.f32 %0, %1, %2;" : "=r"(r) : "f"(b), "f"(a));
    return r;
}
// split pair (a,b) into hi word + lo(residual) word
__device__ __forceinline__ void sp2(float a, float b, uint32_t& whi, uint32_t& wlo) {
    whi = pack2(a, b);
    float ha = __bfloat162float(__float2bfloat16(a));
    float hb = __bfloat162float(__float2bfloat16(b));
    wlo = pack2(a - ha, b - hb);
}

// MUFU-free 2^u for u <= 0. ~2e-6 rel accuracy.
__device__ __forceinline__ float exp2p(float u) {
    u = fmaxf(u, -126.f);
    float z = u + 12582912.f;
    int ki = __float_as_int(z) - 0x4B400000;
    float r = u - (z - 12582912.f);
    float p = 0.00133336f;
    p = fmaf(p, r, 0.00961813f);
    p = fmaf(p, r, 0.05550411f);
    p = fmaf(p, r, 0.24022651f);
    p = fmaf(p, r, 0.69314718f);
    p = fmaf(p, r, 1.0f);
    return __int_as_float(__float_as_int(p) + (ki << 23));
}

// ---------------------------------------------------------------------------
// prep: split fp32 -> bf16 hi/lo planes
// ---------------------------------------------------------------------------
__global__ void __launch_bounds__(256) split_bf(
    const float* __restrict__ in, __nv_bfloat16* __restrict__ oh,
    __nv_bfloat16* __restrict__ ol, int n)
{
    const int i = (blockIdx.x * 256 + threadIdx.x) * 4;
    if (i < n) {
        float4 v = *(const float4*)(in + i);
        float vv[4] = { v.x, v.y, v.z, v.w };
#pragma unroll
        for (int j = 0; j < 4; j++) {
            __nv_bfloat16 h = __float2bfloat16(vv[j]);
            oh[i + j] = h;
            ol[i + j] = __float2bfloat16(vv[j] - __bfloat162float(h));
        }
    }
}

// transpose + split: oh/ol[c][r] = split(in[r][c])
__global__ void __launch_bounds__(256) transpose_split_bf(
    const float* __restrict__ in, __nv_bfloat16* __restrict__ oh,
    __nv_bfloat16* __restrict__ ol, int R, int Cc)
{
    __shared__ float t[32][33];
    const int c0 = blockIdx.x * 32, r0 = blockIdx.y * 32;
    const int x = threadIdx.x, y = threadIdx.y;
#pragma unroll
    for (int i = 0; i < 32; i += 8)
        t[y + i][x] = in[(size_t)(r0 + y + i) * Cc + c0 + x];
    __syncthreads();
#pragma unroll
    for (int i = 0; i < 32; i += 8) {
        float v = t[x][y + i];
        __nv_bfloat16 h = __float2bfloat16(v);
        oh[(size_t)(c0 + y + i) * R + r0 + x] = h;
        ol[(size_t)(c0 + y + i) * R + r0 + x] = __float2bfloat16(v - __bfloat162float(h));
    }
}

// ---------------------------------------------------------------------------
// 3-term bf16 GEMM: C[M,N] = (Ah+Al)[M,K] @ (Bh+Bl)[N,K]^T + bias (drop Al*Bl)
// CTA 128x128x16, 256 thr = 8 warps (2m x 4n), warp 64x32.
// 3-stage cp.async, 1 sync/iter. smem planes: Ah, Al, Bh, Bl (bf16x2 words).
// ---------------------------------------------------------------------------
#define PW 12                            // words per smem row (8 used + pad)
#define PLANE (128 * PW * 4)             // 6144 B
#define STG (4 * PLANE)                  // 24576 B
#define SMEM_GEMM (3 * STG)              // 73728 B
#define PLW (128 * PW)                   // plane size in words

__global__ void __launch_bounds__(256, 2) gemm_bf(
    const __nv_bfloat16* __restrict__ Ah, const __nv_bfloat16* __restrict__ Al,
    const __nv_bfloat16* __restrict__ Bh, const __nv_bfloat16* __restrict__ Bl,
    const float* __restrict__ bias, float* __restrict__ C,
    int N, int K)
{
    extern __shared__ char smem[];
    const uint32_t sb = smem_u32(smem);

    const int tid = threadIdx.x;
    const int lane = tid & 31;
    const int wid = tid >> 5;
    const int wm = (wid & 1) * 64;
    const int wn = (wid >> 1) * 32;
    const int g = lane >> 2;
    const int t = lane & 3;

    const int row0 = blockIdx.y * 128;
    const int col0 = blockIdx.x * 128;

    // loader: plane p = tid>>6 (0:Ah 1:Al 2:Bh 3:Bl); 64 thr/plane, 2 rows each
    const int lp = tid >> 6;
    const int lidx = tid & 63;
    const int lr = lidx * 2;
    const __nv_bfloat16* lbase = (lp == 0) ? Ah : (lp == 1) ? Al : (lp == 2) ? Bh : Bl;
    const int lt0 = (lp < 2) ? row0 : col0;

    float c[4][4][4];
#pragma unroll
    for (int mf = 0; mf < 4; mf++)
#pragma unroll
        for (int nf = 0; nf < 4; nf++)
#pragma unroll
            for (int i = 0; i < 4; i++) c[mf][nf][i] = 0.f;

    const int niter = K / 16;

#define LOAD_STAGE(it, s)                                                    \
    {                                                                        \
        const int k0_ = (it) * 16;                                           \
        const __nv_bfloat16* g0 = lbase + (size_t)(lt0 + lr) * K + k0_;      \
        const uint32_t sa = sb + (s) * STG + lp * PLANE + lr * (PW * 4);     \
        cp_async16(sa, g0);                                                  \
        cp_async16(sa + 16, g0 + 8);                                         \
        cp_async16(sa + PW * 4, g0 + K);                                     \
        cp_async16(sa + PW * 4 + 16, g0 + K + 8);                            \
        CP_COMMIT();                                                         \
    }

    LOAD_STAGE(0, 0);
    LOAD_STAGE(1, 1);
    CP_WAIT(1);
    __syncthreads();

    for (int it = 0; it < niter; it++) {
        const int buf = it % 3;
        const uint32_t* AHs = (const uint32_t*)(smem + buf * STG);
        const uint32_t* ALs = AHs + PLW;
        const uint32_t* BHs = AHs + 2 * PLW;
        const uint32_t* BLs = AHs + 3 * PLW;

        if (it + 2 < niter) LOAD_STAGE(it + 2, (it + 2) % 3);

        uint32_t bh[4][2], bl[4][2];
#pragma unroll
        for (int nf = 0; nf < 4; nf++) {
            const int r = (wn + nf * 8 + g) * PW + t;
            bh[nf][0] = BHs[r]; bh[nf][1] = BHs[r + 4];
            bl[nf][0] = BLs[r]; bl[nf][1] = BLs[r + 4];
        }
#pragma unroll
        for (int mf = 0; mf < 4; mf++) {
            const int r1 = (wm + mf * 16 + g) * PW + t;
            const int r2 = r1 + 8 * PW;
            uint32_t ah[4] = { AHs[r1], AHs[r2], AHs[r1 + 4], AHs[r2 + 4] };
            uint32_t al[4] = { ALs[r1], ALs[r2], ALs[r1 + 4], ALs[r2 + 4] };
#pragma unroll
            for (int nf = 0; nf < 4; nf++) {
                mma_bf(c[mf][nf], ah, bl[nf]);
                mma_bf(c[mf][nf], al, bh[nf]);
                mma_bf(c[mf][nf], ah, bh[nf]);
            }
        }

        if (it + 2 < niter) { CP_WAIT(1); } else { CP_WAIT(0); }
        __syncthreads();
    }
#undef LOAD_STAGE

#pragma unroll
    for (int mf = 0; mf < 4; mf++) {
        const int r0_ = row0 + wm + mf * 16 + g;
#pragma unroll
        for (int nf = 0; nf < 4; nf++) {
            const int cc = col0 + wn + nf * 8 + t * 2;
            const float b0 = bias[cc], b1 = bias[cc + 1];
            float2 lo = make_float2(c[mf][nf][0] + b0, c[mf][nf][1] + b1);
            float2 hi = make_float2(c[mf][nf][2] + b0, c[mf][nf][3] + b1);
            *(float2*)&C[(size_t)r0_ * N + cc]       = lo;
            *(float2*)&C[(size_t)(r0_ + 8) * N + cc] = hi;
        }
    }
}

// ---------------------------------------------------------------------------
// 3-term bf16 flash attention. 4 warps/CTA, 64 q-rows, kv tiles of 64.
// smem word layout (uint32): KH[64][36], KL, VTH[64][36], VTL,
//                            PHI 4x[16][36], PLO 4x[16][36]. 55296 B total.
// ---------------------------------------------------------------------------
#define AP 36
#define KH_W   0
#define KL_W   2304
#define VTH_W  4608
#define VTL_W  6912
#define PHI_W  9216
#define PLO_W  11520
#define ATT_WORDS 13824
#define ATT_SMEM (ATT_WORDS * 4)         // 55296 B

__global__ void __launch_bounds__(128, 4) attn_bf(
    const float* __restrict__ qkv, float* __restrict__ out)
{
    extern __shared__ uint32_t smw[];
    const int tid = threadIdx.x;
    const int lane = tid & 31;
    const int wid = tid >> 5;
    const int g = lane >> 2;
    const int t = lane & 3;

    const int bh_ = blockIdx.y;
    const int b = bh_ >> 4;
    const int h = bh_ & 15;
    const int qtile = (int)gridDim.x - 1 - (int)blockIdx.x;
    const int q0 = qtile * 64;

    const int PHIo = PHI_W + wid * 576;
    const int PLOo = PLO_W + wid * 576;

    const float QS = 0.125f * 1.44269504f;
    const int grow0 = q0 + wid * 16 + g;
    const int grow1 = grow0 + 8;
    const float* q0p = qkv + (size_t)(b * TT + grow0) * C3 + h * HDIM;
    const float* q1p = q0p + (size_t)8 * C3;

    // Q fragments: 4 k16-slabs, packed bf16x2 hi/lo
    uint32_t qh[4][4], ql[4][4];
#pragma unroll
    for (int s = 0; s < 4; s++) {
        const int d0 = 2 * (8 * s + t);
        const int d1 = 2 * (8 * s + t + 4);
        sp2(q0p[d0] * QS, q0p[d0 + 1] * QS, qh[s][0], ql[s][0]);
        sp2(q1p[d0] * QS, q1p[d0 + 1] * QS, qh[s][1], ql[s][1]);
        sp2(q0p[d1] * QS, q0p[d1 + 1] * QS, qh[s][2], ql[s][2]);
        sp2(q1p[d1] * QS, q1p[d1 + 1] * QS, qh[s][3], ql[s][3]);
    }

    float o[8][4];
#pragma unroll
    for (int nf = 0; nf < 8; nf++)
#pragma unroll
        for (int i = 0; i < 4; i++) o[nf][i] = 0.f;
    float m0 = -1e30f, m1 = -1e30f, l0 = 0.f, l1 = 0.f;

    const int ntiles = qtile + 1;
    const float* kbase0 = qkv + (size_t)b * TT * C3 + CCH + h * HDIM;

    for (int tile = 0; tile < ntiles; tile++) {
        const int kv0 = tile * 64;
        const float* kb = kbase0 + (size_t)kv0 * C3;

        __syncthreads();

        // stage K: [kv][d] hi/lo planes, d packed in pairs
#pragma unroll
        for (int i = 0; i < 8; i++) {
            const int idx = tid + i * 128;          // 1024 float4s
            const int r = idx >> 4, c4 = idx & 15;
            float4 kv4 = *(const float4*)(kb + (size_t)r * C3 + c4 * 4);
            uint32_t h0, l0w, h1, l1w;
            sp2(kv4.x, kv4.y, h0, l0w);
            sp2(kv4.z, kv4.w, h1, l1w);
            const int w = r * AP + c4 * 2;
            smw[KH_W + w] = h0; smw[KH_W + w + 1] = h1;
            smw[KL_W + w] = l0w; smw[KL_W + w + 1] = l1w;
        }
        // stage V transposed: [d][kv] hi/lo planes, kv packed in pairs
#pragma unroll
        for (int j = 0; j < 2; j++) {
            const int bb2 = tid + j * 128;          // 256 4x4 blocks
            const int br = (bb2 >> 4) * 4;          // kv base
            const int bc = (bb2 & 15) * 4;          // d base
            const float* vb = kb + CCH;
            float4 v0 = *(const float4*)(vb + (size_t)(br + 0) * C3 + bc);
            float4 v1 = *(const float4*)(vb + (size_t)(br + 1) * C3 + bc);
            float4 v2 = *(const float4*)(vb + (size_t)(br + 2) * C3 + bc);
            float4 v3 = *(const float4*)(vb + (size_t)(br + 3) * C3 + bc);
            float4 rowv[4] = {
                make_float4(v0.x, v1.x, v2.x, v3.x),
                make_float4(v0.y, v1.y, v2.y, v3.y),
                make_float4(v0.z, v1.z, v2.z, v3.z),
                make_float4(v0.w, v1.w, v2.w, v3.w)
            };
#pragma unroll
            for (int d = 0; d < 4; d++) {
                uint32_t h0, l0w, h1, l1w;
                sp2(rowv[d].x, rowv[d].y, h0, l0w);
                sp2(rowv[d].z, rowv[d].w, h1, l1w);
                const int w = (bc + d) * AP + (br >> 1);
                smw[VTH_W + w] = h0; smw[VTH_W + w + 1] = h1;
                smw[VTL_W + w] = l0w; smw[VTL_W + w + 1] = l1w;
            }
        }
        __syncthreads();

        // S = Q K^T (3-term bf16), log2-domain
        float s[8][4];
#pragma unroll
        for (int nf = 0; nf < 8; nf++) {
#pragma unroll
            for (int i = 0; i < 4; i++) s[nf][i] = 0.f;
            const int kr = (nf * 8 + g) * AP;
#pragma unroll
            for (int sl = 0; sl < 4; sl++) {
                uint32_t kh2[2] = { smw[KH_W + kr + 8 * sl + t], smw[KH_W + kr + 8 * sl + t + 4] };
                uint32_t kl2[2] = { smw[KL_W + kr + 8 * sl + t], smw[KL_W + kr + 8 * sl + t + 4] };
                mma_bf(s[nf], qh[sl], kl2);
                mma_bf(s[nf], ql[sl], kh2);
                mma_bf(s[nf], qh[sl], kh2);
            }
        }

        // causal mask (diagonal tile only)
        if (tile == qtile) {
#pragma unroll
            for (int nf = 0; nf < 8; nf++) {
                const int c0 = kv0 + nf * 8 + 2 * t;
                if (c0 > grow0)     s[nf][0] = -1e30f;
                if (c0 + 1 > grow0) s[nf][1] = -1e30f;
                if (c0 > grow1)     s[nf][2] = -1e30f;
                if (c0 + 1 > grow1) s[nf][3] = -1e30f;
            }
        }

        // online softmax (base 2)
        float tm0 = -1e30f, tm1 = -1e30f;
#pragma unroll
        for (int nf = 0; nf < 8; nf++) {
            tm0 = fmaxf(tm0, fmaxf(s[nf][0], s[nf][1]));
            tm1 = fmaxf(tm1, fmaxf(s[nf][2], s[nf][3]));
        }
        tm0 = fmaxf(tm0, __shfl_xor_sync(0xffffffffu, tm0, 1));
        tm0 = fmaxf(tm0, __shfl_xor_sync(0xffffffffu, tm0, 2));
        tm1 = fmaxf(tm1, __shfl_xor_sync(0xffffffffu, tm1, 1));
        tm1 = fmaxf(tm1, __shfl_xor_sync(0xffffffffu, tm1, 2));
        const float mn0 = fmaxf(m0, tm0);
        const float mn1 = fmaxf(m1, tm1);
        const float cr0 = exp2p(m0 - mn0);
        const float cr1 = exp2p(m1 - mn1);
        m0 = mn0; m1 = mn1;
        l0 *= cr0; l1 *= cr1;
#pragma unroll
        for (int nf = 0; nf < 8; nf++) {
            o[nf][0] *= cr0; o[nf][1] *= cr0;
            o[nf][2] *= cr1; o[nf][3] *= cr1;
        }

        // P = 2^(s-m), split hi/lo packed pairs to per-warp smem
#pragma unroll
        for (int nf = 0; nf < 8; nf++) {
            const float p0 = exp2p(s[nf][0] - m0);
            const float p1 = exp2p(s[nf][1] - m0);
            const float p2 = exp2p(s[nf][2] - m1);
            const float p3 = exp2p(s[nf][3] - m1);
            l0 += p0 + p1;
            l1 += p2 + p3;
            uint32_t w0h, w0l, w1h, w1l;
            sp2(p0, p1, w0h, w0l);
            sp2(p2, p3, w1h, w1l);
            const int w = 4 * nf + t;
            smw[PHIo + g * AP + w] = w0h;
            smw[PLOo + g * AP + w] = w0l;
            smw[PHIo + (g + 8) * AP + w] = w1h;
            smw[PLOo + (g + 8) * AP + w] = w1l;
        }
        __syncwarp();

        // O += P V (3-term bf16)
#pragma unroll
        for (int sl = 0; sl < 4; sl++) {
            const int pb1 = PHIo + g * AP + 8 * sl;
            const int pb2 = PHIo + (g + 8) * AP + 8 * sl;
            const int qb1 = PLOo + g * AP + 8 * sl;
            const int qb2 = PLOo + (g + 8) * AP + 8 * sl;
            uint32_t pah[4] = { smw[pb1 + t], smw[pb2 + t], smw[pb1 + t + 4], smw[pb2 + t + 4] };
            uint32_t pal[4] = { smw[qb1 + t], smw[qb2 + t], smw[qb1 + t + 4], smw[qb2 + t + 4] };
#pragma unroll
            for (int nf = 0; nf < 8; nf++) {
                const int vr = (nf * 8 + g) * AP + 8 * sl;
                uint32_t vh[2] = { smw[VTH_W + vr + t], smw[VTH_W + vr + t + 4] };
                uint32_t vl[2] = { smw[VTL_W + vr + t], smw[VTL_W + vr + t + 4] };
                mma_bf(o[nf], pah, vl);
                mma_bf(o[nf], pal, vh);
                mma_bf(o[nf], pah, vh);
            }
        }
        __syncwarp();
    }

    l0 += __shfl_xor_sync(0xffffffffu, l0, 1);
    l0 += __shfl_xor_sync(0xffffffffu, l0, 2);
    l1 += __shfl_xor_sync(0xffffffffu, l1, 1);
    l1 += __shfl_xor_sync(0xffffffffu, l1, 2);
    const float inv0 = 1.f / l0;
    const float inv1 = 1.f / l1;

    float* op0 = out + (size_t)(b * TT + grow0) * CCH + h * HDIM;
    float* op1 = out + (size_t)(b * TT + grow1) * CCH + h * HDIM;
#pragma unroll
    for (int nf = 0; nf < 8; nf++) {
        const int cidx = nf * 8 + 2 * t;
        *(float2*)&op0[cidx] = make_float2(o[nf][0] * inv0, o[nf][1] * inv0);
        *(float2*)&op1[cidx] = make_float2(o[nf][2] * inv1, o[nf][3] * inv1);
    }
}

// ---------------------------------------------------------------------------
extern "C" void kernel_launch(void* const* d_in, const int* in_sizes, int n_in,
                              void* d_out, int out_size)
{
    (void)in_sizes; (void)n_in; (void)out_size;
    const float* x    = (const float*)d_in[0];
    const float* Wqkv = (const float*)d_in[1];
    const float* bqkv = (const float*)d_in[2];
    const float* Wo   = (const float*)d_in[3];
    const float* bo   = (const float*)d_in[4];
    float* out = (float*)d_out;

    float *qkvbuf, *attbuf;
    __nv_bfloat16 *xh, *xl, *ath, *atl, *wqh, *wql, *woh, *wol;
    cudaGetSymbolAddress((void**)&qkvbuf, g_qkv);
    cudaGetSymbolAddress((void**)&attbuf, g_att);
    cudaGetSymbolAddress((void**)&xh,  g_xh);
    cudaGetSymbolAddress((void**)&xl,  g_xl);
    cudaGetSymbolAddress((void**)&ath, g_ath);
    cudaGetSymbolAddress((void**)&atl, g_atl);
    cudaGetSymbolAddress((void**)&wqh, g_wqh);
    cudaGetSymbolAddress((void**)&wql, g_wql);
    cudaGetSymbolAddress((void**)&woh, g_woh);
    cudaGetSymbolAddress((void**)&wol, g_wol);

    static int smem_set = 0;
    if (!smem_set) {
        cudaFuncSetAttribute(gemm_bf, cudaFuncAttributeMaxDynamicSharedMemorySize, SMEM_GEMM);
        cudaFuncSetAttribute(attn_bf, cudaFuncAttributeMaxDynamicSharedMemorySize, ATT_SMEM);
        smem_set = 1;
    }

    // 0) prep: transpose+split weights, split x
    transpose_split_bf<<<dim3(C3 / 32, CCH / 32), dim3(32, 8)>>>(Wqkv, wqh, wql, CCH, C3);
    transpose_split_bf<<<dim3(CCH / 32, CCH / 32), dim3(32, 8)>>>(Wo, woh, wol, CCH, CCH);
    split_bf<<<(NTOK * CCH / 4 + 255) / 256, 256>>>(x, xh, xl, NTOK * CCH);

    // 1) QKV projection (3-term bf16)
    gemm_bf<<<dim3(C3 / 128, NTOK / 128), 256, SMEM_GEMM>>>(xh, xl, wqh, wql, bqkv, qkvbuf, C3, CCH);

    // 2) causal flash attention (3-term bf16)
    attn_bf<<<dim3(TT / 64, BB * HH), 128, ATT_SMEM>>>(qkvbuf, attbuf);

    // 3) split attention output, then output projection (3-term bf16)
    split_bf<<<(NTOK * CCH / 4 + 255) / 256, 256>>>(attbuf, ath, atl, NTOK * CCH);
    gemm_bf<<<dim3(CCH / 128, NTOK / 128), 256, SMEM_GEMM>>>(ath, atl, woh, wol, bo, out, CCH, CCH);
}

// round 12
// speedup vs baseline: 1.8138x; 1.2054x over previous
#include <cuda_runtime.h>
#include <cuda_bf16.h>
#include <cstdint>

// Problem constants
#define BB   2
#define TT   2048
#define CCH  1024
#define HH   16
#define HDIM 64
#define NTOK (BB * TT)     // 4096
#define C3   (3 * CCH)     // 3072

// Scratch (allocation-free rule: __device__ globals)
__device__ float g_qkv[(size_t)NTOK * C3];    // [4096, 3072] fp32
__device__ float g_att[(size_t)NTOK * CCH];   // [4096, 1024] fp32
__device__ __nv_bfloat16 g_xh[(size_t)NTOK * CCH];
__device__ __nv_bfloat16 g_xl[(size_t)NTOK * CCH];
__device__ __nv_bfloat16 g_ath[(size_t)NTOK * CCH];
__device__ __nv_bfloat16 g_atl[(size_t)NTOK * CCH];
__device__ __nv_bfloat16 g_wqh[(size_t)C3 * CCH];   // Wqkv^T hi [3072][1024]
__device__ __nv_bfloat16 g_wql[(size_t)C3 * CCH];
__device__ __nv_bfloat16 g_woh[(size_t)CCH * CCH];  // Wo^T hi
__device__ __nv_bfloat16 g_wol[(size_t)CCH * CCH];

// ---------------------------------------------------------------------------
// helpers
// ---------------------------------------------------------------------------
__device__ __forceinline__ uint32_t smem_u32(const void* p) {
    uint32_t a;
    asm("{ .reg .u64 t; cvta.to.shared.u64 t, %1; cvt.u32.u64 %0, t; }" : "=r"(a) : "l"(p));
    return a;
}
__device__ __forceinline__ void cp_async16(uint32_t saddr, const void* gaddr) {
    asm volatile("cp.async.ca.shared.global [%0], [%1], 16;" :: "r"(saddr), "l"(gaddr) : "memory");
}
#define CP_COMMIT() asm volatile("cp.async.commit_group;" ::: "memory")
#define CP_WAIT(n)  asm volatile("cp.async.wait_group %0;" :: "n"(n) : "memory")

// bf16 m16n8k16 mma, fp32 accumulate
__device__ __forceinline__ void mma_bf(float* c, const uint32_t* a, const uint32_t* b) {
    asm volatile(
        "mma.sync.aligned.m16n8k16.row.col.f32.bf16.bf16.f32 "
        "{%0,%1,%2,%3}, {%4,%5,%6,%7}, {%8,%9}, {%0,%1,%2,%3};"
        : "+f"(c[0]), "+f"(c[1]), "+f"(c[2]), "+f"(c[3])
        : "r"(a[0]), "r"(a[1]), "r"(a[2]), "r"(a[3]), "r"(b[0]), "r"(b[1]));
}

// ldmatrix x4 (b16)
__device__ __forceinline__ void ldm4(uint32_t& r0, uint32_t& r1, uint32_t& r2, uint32_t& r3,
                                     uint32_t addr) {
    asm volatile("ldmatrix.sync.aligned.m8n8.x4.shared.b16 {%0,%1,%2,%3}, [%4];"
                 : "=r"(r0), "=r"(r1), "=r"(r2), "=r"(r3) : "r"(addr));
}

// pack two floats -> bf16x2 (a LOW, b HIGH)
__device__ __forceinline__ uint32_t pack2(float a, float b) {
    uint32_t r;
    asm("cvt.rn.bf16x2.f32 %0, %1, %2;" : "=r"(r) : "f"(b), "f"(a));
    return r;
}
__device__ __forceinline__ void sp2(float a, float b, uint32_t& whi, uint32_t& wlo) {
    whi = pack2(a, b);
    float ha = __bfloat162float(__float2bfloat16(a));
    float hb = __bfloat162float(__float2bfloat16(b));
    wlo = pack2(a - ha, b - hb);
}

// MUFU-free 2^u for u <= 0. ~2e-6 rel accuracy.
__device__ __forceinline__ float exp2p(float u) {
    u = fmaxf(u, -126.f);
    float z = u + 12582912.f;
    int ki = __float_as_int(z) - 0x4B400000;
    float r = u - (z - 12582912.f);
    float p = 0.00133336f;
    p = fmaf(p, r, 0.00961813f);
    p = fmaf(p, r, 0.05550411f);
    p = fmaf(p, r, 0.24022651f);
    p = fmaf(p, r, 0.69314718f);
    p = fmaf(p, r, 1.0f);
    return __int_as_float(__float_as_int(p) + (ki << 23));
}

// ---------------------------------------------------------------------------
// prep kernels
// ---------------------------------------------------------------------------
__global__ void __launch_bounds__(256) split_bf(
    const float* __restrict__ in, __nv_bfloat16* __restrict__ oh,
    __nv_bfloat16* __restrict__ ol, int n)
{
    const int i = (blockIdx.x * 256 + threadIdx.x) * 4;
    if (i < n) {
        float4 v = *(const float4*)(in + i);
        float vv[4] = { v.x, v.y, v.z, v.w };
#pragma unroll
        for (int j = 0; j < 4; j++) {
            __nv_bfloat16 h = __float2bfloat16(vv[j]);
            oh[i + j] = h;
            ol[i + j] = __float2bfloat16(vv[j] - __bfloat162float(h));
        }
    }
}

__global__ void __launch_bounds__(256) transpose_split_bf(
    const float* __restrict__ in, __nv_bfloat16* __restrict__ oh,
    __nv_bfloat16* __restrict__ ol, int R, int Cc)
{
    __shared__ float t[32][33];
    const int c0 = blockIdx.x * 32, r0 = blockIdx.y * 32;
    const int x = threadIdx.x, y = threadIdx.y;
#pragma unroll
    for (int i = 0; i < 32; i += 8)
        t[y + i][x] = in[(size_t)(r0 + y + i) * Cc + c0 + x];
    __syncthreads();
#pragma unroll
    for (int i = 0; i < 32; i += 8) {
        float v = t[x][y + i];
        __nv_bfloat16 h = __float2bfloat16(v);
        oh[(size_t)(c0 + y + i) * R + r0 + x] = h;
        ol[(size_t)(c0 + y + i) * R + r0 + x] = __float2bfloat16(v - __bfloat162float(h));
    }
}

// ---------------------------------------------------------------------------
// 3-term bf16 GEMM with ldmatrix fragment loads.
// C[M,N] = (Ah+Al)[M,K] @ (Bh+Bl)[N,K]^T + bias (drop Al*Bl)
// CTA 128x128x16, 256 thr = 8 warps (2m x 4n), warp 64x32, 3-stage cp.async.
// ---------------------------------------------------------------------------
#define PW 12                            // words per smem row
#define PLANE (128 * PW * 4)             // 6144 B
#define STG (4 * PLANE)                  // 24576 B
#define SMEM_GEMM (3 * STG)              // 73728 B
#define PLW (128 * PW)

__global__ void __launch_bounds__(256, 2) gemm_bf(
    const __nv_bfloat16* __restrict__ Ah, const __nv_bfloat16* __restrict__ Al,
    const __nv_bfloat16* __restrict__ Bh, const __nv_bfloat16* __restrict__ Bl,
    const float* __restrict__ bias, float* __restrict__ C,
    int N, int K)
{
    extern __shared__ char smem[];
    const uint32_t sb = smem_u32(smem);

    const int tid = threadIdx.x;
    const int lane = tid & 31;
    const int wid = tid >> 5;
    const int wm = (wid & 1) * 64;
    const int wn = (wid >> 1) * 32;
    const int g = lane >> 2;
    const int t = lane & 3;

    const int row0 = blockIdx.y * 128;
    const int col0 = blockIdx.x * 128;

    // ldmatrix per-lane base offsets (bytes, within a plane)
    // A: row = wm + mf*16 + (lane&15), chunk = (lane>>4)*16B
    const uint32_t aoff = (uint32_t)((wm + (lane & 15)) * PW) * 4 + ((lane >> 4) << 4);
    // B: row = wn + np*16 + (lane&7) + ((lane>>4)<<3), chunk = ((lane>>3)&1)*16B
    const uint32_t boff = (uint32_t)((wn + (lane & 7) + ((lane >> 4) << 3)) * PW) * 4
                          + (((lane >> 3) & 1) << 4);

    // loader: plane p = tid>>6; 64 thr/plane, 2 rows each
    const int lp = tid >> 6;
    const int lr = (tid & 63) * 2;
    const __nv_bfloat16* lbase = (lp == 0) ? Ah : (lp == 1) ? Al : (lp == 2) ? Bh : Bl;
    const int lt0 = (lp < 2) ? row0 : col0;

    float c[4][4][4];
#pragma unroll
    for (int mf = 0; mf < 4; mf++)
#pragma unroll
        for (int nf = 0; nf < 4; nf++)
#pragma unroll
            for (int i = 0; i < 4; i++) c[mf][nf][i] = 0.f;

    const int niter = K / 16;

#define LOAD_STAGE(it, s)                                                    \
    {                                                                        \
        const int k0_ = (it) * 16;                                           \
        const __nv_bfloat16* g0 = lbase + (size_t)(lt0 + lr) * K + k0_;      \
        const uint32_t sa = sb + (s) * STG + lp * PLANE + lr * (PW * 4);     \
        cp_async16(sa, g0);                                                  \
        cp_async16(sa + 16, g0 + 8);                                         \
        cp_async16(sa + PW * 4, g0 + K);                                     \
        cp_async16(sa + PW * 4 + 16, g0 + K + 8);                            \
        CP_COMMIT();                                                         \
    }

    LOAD_STAGE(0, 0);
    LOAD_STAGE(1, 1);
    CP_WAIT(1);
    __syncthreads();

    for (int it = 0; it < niter; it++) {
        const int buf = it % 3;
        const uint32_t sA_h = sb + buf * STG + aoff;
        const uint32_t sA_l = sA_h + PLANE;
        const uint32_t sB_h = sb + buf * STG + 2 * PLANE + boff;
        const uint32_t sB_l = sB_h + PLANE;

        if (it + 2 < niter) LOAD_STAGE(it + 2, (it + 2) % 3);

        // B fragments: 2 nf per ldmatrix.x4
        uint32_t bh[4][2], bl[4][2];
#pragma unroll
        for (int np = 0; np < 2; np++) {
            ldm4(bh[2 * np][0], bh[2 * np][1], bh[2 * np + 1][0], bh[2 * np + 1][1],
                 sB_h + np * (16 * PW * 4));
            ldm4(bl[2 * np][0], bl[2 * np][1], bl[2 * np + 1][0], bl[2 * np + 1][1],
                 sB_l + np * (16 * PW * 4));
        }
#pragma unroll
        for (int mf = 0; mf < 4; mf++) {
            uint32_t ah[4], al[4];
            ldm4(ah[0], ah[1], ah[2], ah[3], sA_h + mf * (16 * PW * 4));
            ldm4(al[0], al[1], al[2], al[3], sA_l + mf * (16 * PW * 4));
#pragma unroll
            for (int nf = 0; nf < 4; nf++) {
                mma_bf(c[mf][nf], ah, bl[nf]);
                mma_bf(c[mf][nf], al, bh[nf]);
                mma_bf(c[mf][nf], ah, bh[nf]);
            }
        }

        if (it + 2 < niter) { CP_WAIT(1); } else { CP_WAIT(0); }
        __syncthreads();
    }
#undef LOAD_STAGE

#pragma unroll
    for (int mf = 0; mf < 4; mf++) {
        const int r0_ = row0 + wm + mf * 16 + g;
#pragma unroll
        for (int nf = 0; nf < 4; nf++) {
            const int cc = col0 + wn + nf * 8 + t * 2;
            const float b0 = bias[cc], b1 = bias[cc + 1];
            float2 lo = make_float2(c[mf][nf][0] + b0, c[mf][nf][1] + b1);
            float2 hi = make_float2(c[mf][nf][2] + b0, c[mf][nf][3] + b1);
            *(float2*)&C[(size_t)r0_ * N + cc]       = lo;
            *(float2*)&C[(size_t)(r0_ + 8) * N + cc] = hi;
        }
    }
}

// ---------------------------------------------------------------------------
// 3-term bf16 flash attention with ldmatrix fragment loads.
// 4 warps/CTA, 64 q-rows, kv tiles of 64.
// smem words: KH[64][36], KL, VTH[64][36], VTL, PHI 4x[16][36], PLO 4x[16][36]
// ---------------------------------------------------------------------------
#define AP 36
#define KH_W   0
#define KL_W   2304
#define VTH_W  4608
#define VTL_W  6912
#define PHI_W  9216
#define PLO_W  11520
#define ATT_WORDS 13824
#define ATT_SMEM (ATT_WORDS * 4)         // 55296 B

__global__ void __launch_bounds__(128, 4) attn_bf(
    const float* __restrict__ qkv, float* __restrict__ out)
{
    extern __shared__ uint32_t smw[];
    const uint32_t sb = smem_u32(smw);
    const int tid = threadIdx.x;
    const int lane = tid & 31;
    const int wid = tid >> 5;
    const int g = lane >> 2;
    const int t = lane & 3;

    const int bh_ = blockIdx.y;
    const int b = bh_ >> 4;
    const int h = bh_ & 15;
    const int qtile = (int)gridDim.x - 1 - (int)blockIdx.x;
    const int q0 = qtile * 64;

    const int PHIo = PHI_W + wid * 576;
    const int PLOo = PLO_W + wid * 576;

    // ldmatrix per-lane base offsets (bytes)
    // B-style (K, VT): row = base + (lane&7) + ((lane>>4)<<3), chunk ((lane>>3)&1)*16
    const uint32_t bRowOff = (uint32_t)(((lane & 7) + ((lane >> 4) << 3)) * AP) * 4
                             + (((lane >> 3) & 1) << 4);
    const uint32_t kAddr  = sb + KH_W * 4 + bRowOff;
    const uint32_t klAddr = sb + KL_W * 4 + bRowOff;
    const uint32_t vAddr  = sb + VTH_W * 4 + bRowOff;
    const uint32_t vlAddr = sb + VTL_W * 4 + bRowOff;
    // A-style (P): row = lane&15, chunk (lane>>4)*16
    const uint32_t pOffA = (uint32_t)((lane & 15) * AP) * 4 + ((lane >> 4) << 4);
    const uint32_t phAddr = sb + PHIo * 4 + pOffA;
    const uint32_t plAddr = sb + PLOo * 4 + pOffA;

    const float QS = 0.125f * 1.44269504f;
    const int grow0 = q0 + wid * 16 + g;
    const int grow1 = grow0 + 8;
    const float* q0p = qkv + (size_t)(b * TT + grow0) * C3 + h * HDIM;
    const float* q1p = q0p + (size_t)8 * C3;

    uint32_t qh[4][4], ql[4][4];
#pragma unroll
    for (int s = 0; s < 4; s++) {
        const int d0 = 2 * (8 * s + t);
        const int d1 = 2 * (8 * s + t + 4);
        sp2(q0p[d0] * QS, q0p[d0 + 1] * QS, qh[s][0], ql[s][0]);
        sp2(q1p[d0] * QS, q1p[d0 + 1] * QS, qh[s][1], ql[s][1]);
        sp2(q0p[d1] * QS, q0p[d1 + 1] * QS, qh[s][2], ql[s][2]);
        sp2(q1p[d1] * QS, q1p[d1 + 1] * QS, qh[s][3], ql[s][3]);
    }

    float o[8][4];
#pragma unroll
    for (int nf = 0; nf < 8; nf++)
#pragma unroll
        for (int i = 0; i < 4; i++) o[nf][i] = 0.f;
    float m0 = -1e30f, m1 = -1e30f, l0 = 0.f, l1 = 0.f;

    const int ntiles = qtile + 1;
    const float* kbase0 = qkv + (size_t)b * TT * C3 + CCH + h * HDIM;

    for (int tile = 0; tile < ntiles; tile++) {
        const int kv0 = tile * 64;
        const float* kb = kbase0 + (size_t)kv0 * C3;

        __syncthreads();

        // stage K hi/lo (rows kv, d packed in pairs)
#pragma unroll
        for (int i = 0; i < 8; i++) {
            const int idx = tid + i * 128;
            const int r = idx >> 4, c4 = idx & 15;
            float4 kv4 = *(const float4*)(kb + (size_t)r * C3 + c4 * 4);
            uint32_t h0, l0w, h1, l1w;
            sp2(kv4.x, kv4.y, h0, l0w);
            sp2(kv4.z, kv4.w, h1, l1w);
            const int w = r * AP + c4 * 2;
            smw[KH_W + w] = h0; smw[KH_W + w + 1] = h1;
            smw[KL_W + w] = l0w; smw[KL_W + w + 1] = l1w;
        }
        // stage V transposed hi/lo (rows d, kv packed in pairs)
#pragma unroll
        for (int j = 0; j < 2; j++) {
            const int bb2 = tid + j * 128;
            const int br = (bb2 >> 4) * 4;
            const int bc = (bb2 & 15) * 4;
            const float* vb = kb + CCH;
            float4 v0 = *(const float4*)(vb + (size_t)(br + 0) * C3 + bc);
            float4 v1 = *(const float4*)(vb + (size_t)(br + 1) * C3 + bc);
            float4 v2 = *(const float4*)(vb + (size_t)(br + 2) * C3 + bc);
            float4 v3 = *(const float4*)(vb + (size_t)(br + 3) * C3 + bc);
            float4 rowv[4] = {
                make_float4(v0.x, v1.x, v2.x, v3.x),
                make_float4(v0.y, v1.y, v2.y, v3.y),
                make_float4(v0.z, v1.z, v2.z, v3.z),
                make_float4(v0.w, v1.w, v2.w, v3.w)
            };
#pragma unroll
            for (int d = 0; d < 4; d++) {
                uint32_t h0, l0w, h1, l1w;
                sp2(rowv[d].x, rowv[d].y, h0, l0w);
                sp2(rowv[d].z, rowv[d].w, h1, l1w);
                const int w = (bc + d) * AP + (br >> 1);
                smw[VTH_W + w] = h0; smw[VTH_W + w + 1] = h1;
                smw[VTL_W + w] = l0w; smw[VTL_W + w + 1] = l1w;
            }
        }
        __syncthreads();

        // S = Q K^T (3-term bf16), ldmatrix K-frags (2 nf per x4)
        float s[8][4];
#pragma unroll
        for (int nf = 0; nf < 8; nf++)
#pragma unroll
            for (int i = 0; i < 4; i++) s[nf][i] = 0.f;
#pragma unroll
        for (int sl = 0; sl < 4; sl++) {
            const uint32_t slo = sl * 32;
#pragma unroll
            for (int np = 0; np < 4; np++) {
                uint32_t kh0, kh1, kh2w, kh3, kl0, kl1, kl2w, kl3;
                ldm4(kh0, kh1, kh2w, kh3, kAddr + np * (16 * AP * 4) + slo);
                ldm4(kl0, kl1, kl2w, kl3, klAddr + np * (16 * AP * 4) + slo);
                uint32_t bh0[2] = { kh0, kh1 }, bh1[2] = { kh2w, kh3 };
                uint32_t bl0[2] = { kl0, kl1 }, bl1[2] = { kl2w, kl3 };
                mma_bf(s[2 * np],     qh[sl], bl0);
                mma_bf(s[2 * np],     ql[sl], bh0);
                mma_bf(s[2 * np],     qh[sl], bh0);
                mma_bf(s[2 * np + 1], qh[sl], bl1);
                mma_bf(s[2 * np + 1], ql[sl], bh1);
                mma_bf(s[2 * np + 1], qh[sl], bh1);
            }
        }

        // causal mask (diagonal tile only)
        if (tile == qtile) {
#pragma unroll
            for (int nf = 0; nf < 8; nf++) {
                const int c0 = kv0 + nf * 8 + 2 * t;
                if (c0 > grow0)     s[nf][0] = -1e30f;
                if (c0 + 1 > grow0) s[nf][1] = -1e30f;
                if (c0 > grow1)     s[nf][2] = -1e30f;
                if (c0 + 1 > grow1) s[nf][3] = -1e30f;
            }
        }

        // online softmax (base 2)
        float tm0 = -1e30f, tm1 = -1e30f;
#pragma unroll
        for (int nf = 0; nf < 8; nf++) {
            tm0 = fmaxf(tm0, fmaxf(s[nf][0], s[nf][1]));
            tm1 = fmaxf(tm1, fmaxf(s[nf][2], s[nf][3]));
        }
        tm0 = fmaxf(tm0, __shfl_xor_sync(0xffffffffu, tm0, 1));
        tm0 = fmaxf(tm0, __shfl_xor_sync(0xffffffffu, tm0, 2));
        tm1 = fmaxf(tm1, __shfl_xor_sync(0xffffffffu, tm1, 1));
        tm1 = fmaxf(tm1, __shfl_xor_sync(0xffffffffu, tm1, 2));
        const float mn0 = fmaxf(m0, tm0);
        const float mn1 = fmaxf(m1, tm1);
        const float cr0 = exp2p(m0 - mn0);
        const float cr1 = exp2p(m1 - mn1);
        m0 = mn0; m1 = mn1;
        l0 *= cr0; l1 *= cr1;
#pragma unroll
        for (int nf = 0; nf < 8; nf++) {
            o[nf][0] *= cr0; o[nf][1] *= cr0;
            o[nf][2] *= cr1; o[nf][3] *= cr1;
        }

        // P = 2^(s-m), split hi/lo packed pairs to per-warp smem
#pragma unroll
        for (int nf = 0; nf < 8; nf++) {
            const float p0 = exp2p(s[nf][0] - m0);
            const float p1 = exp2p(s[nf][1] - m0);
            const float p2 = exp2p(s[nf][2] - m1);
            const float p3 = exp2p(s[nf][3] - m1);
            l0 += p0 + p1;
            l1 += p2 + p3;
            uint32_t w0h, w0l, w1h, w1l;
            sp2(p0, p1, w0h, w0l);
            sp2(p2, p3, w1h, w1l);
            const int w = 4 * nf + t;
            smw[PHIo + g * AP + w] = w0h;
            smw[PLOo + g * AP + w] = w0l;
            smw[PHIo + (g + 8) * AP + w] = w1h;
            smw[PLOo + (g + 8) * AP + w] = w1l;
        }
        __syncwarp();

        // O += P V (3-term bf16), ldmatrix P (A-style) and VT (B-style)
#pragma unroll
        for (int sl = 0; sl < 4; sl++) {
            const uint32_t slo = sl * 32;
            uint32_t ph[4], pl[4];
            ldm4(ph[0], ph[1], ph[2], ph[3], phAddr + slo);
            ldm4(pl[0], pl[1], pl[2], pl[3], plAddr + slo);
#pragma unroll
            for (int np = 0; np < 4; np++) {
                uint32_t vh0, vh1, vh2w, vh3, vl0, vl1, vl2w, vl3;
                ldm4(vh0, vh1, vh2w, vh3, vAddr + np * (16 * AP * 4) + slo);
                ldm4(vl0, vl1, vl2w, vl3, vlAddr + np * (16 * AP * 4) + slo);
                uint32_t bh0[2] = { vh0, vh1 }, bh1[2] = { vh2w, vh3 };
                uint32_t bl0[2] = { vl0, vl1 }, bl1[2] = { vl2w, vl3 };
                mma_bf(o[2 * np],     ph, bl0);
                mma_bf(o[2 * np],     pl, bh0);
                mma_bf(o[2 * np],     ph, bh0);
                mma_bf(o[2 * np + 1], ph, bl1);
                mma_bf(o[2 * np + 1], pl, bh1);
                mma_bf(o[2 * np + 1], ph, bh1);
            }
        }
        __syncwarp();
    }

    l0 += __shfl_xor_sync(0xffffffffu, l0, 1);
    l0 += __shfl_xor_sync(0xffffffffu, l0, 2);
    l1 += __shfl_xor_sync(0xffffffffu, l1, 1);
    l1 += __shfl_xor_sync(0xffffffffu, l1, 2);
    const float inv0 = 1.f / l0;
    const float inv1 = 1.f / l1;

    float* op0 = out + (size_t)(b * TT + grow0) * CCH + h * HDIM;
    float* op1 = out + (size_t)(b * TT + grow1) * CCH + h * HDIM;
#pragma unroll
    for (int nf = 0; nf < 8; nf++) {
        const int cidx = nf * 8 + 2 * t;
        *(float2*)&op0[cidx] = make_float2(o[nf][0] * inv0, o[nf][1] * inv0);
        *(float2*)&op1[cidx] = make_float2(o[nf][2] * inv1, o[nf][3] * inv1);
    }
}

// ---------------------------------------------------------------------------
extern "C" void kernel_launch(void* const* d_in, const int* in_sizes, int n_in,
                              void* d_out, int out_size)
{
    (void)in_sizes; (void)n_in; (void)out_size;
    const float* x    = (const float*)d_in[0];
    const float* Wqkv = (const float*)d_in[1];
    const float* bqkv = (const float*)d_in[2];
    const float* Wo   = (const float*)d_in[3];
    const float* bo   = (const float*)d_in[4];
    float* out = (float*)d_out;

    float *qkvbuf, *attbuf;
    __nv_bfloat16 *xh, *xl, *ath, *atl, *wqh, *wql, *woh, *wol;
    cudaGetSymbolAddress((void**)&qkvbuf, g_qkv);
    cudaGetSymbolAddress((void**)&attbuf, g_att);
    cudaGetSymbolAddress((void**)&xh,  g_xh);
    cudaGetSymbolAddress((void**)&xl,  g_xl);
    cudaGetSymbolAddress((void**)&ath, g_ath);
    cudaGetSymbolAddress((void**)&atl, g_atl);
    cudaGetSymbolAddress((void**)&wqh, g_wqh);
    cudaGetSymbolAddress((void**)&wql, g_wql);
    cudaGetSymbolAddress((void**)&woh, g_woh);
    cudaGetSymbolAddress((void**)&wol, g_wol);

    static int smem_set = 0;
    if (!smem_set) {
        cudaFuncSetAttribute(gemm_bf, cudaFuncAttributeMaxDynamicSharedMemorySize, SMEM_GEMM);
        cudaFuncSetAttribute(attn_bf, cudaFuncAttributeMaxDynamicSharedMemorySize, ATT_SMEM);
        smem_set = 1;
    }

    // 0) prep
    transpose_split_bf<<<dim3(C3 / 32, CCH / 32), dim3(32, 8)>>>(Wqkv, wqh, wql, CCH, C3);
    transpose_split_bf<<<dim3(CCH / 32, CCH / 32), dim3(32, 8)>>>(Wo, woh, wol, CCH, CCH);
    split_bf<<<(NTOK * CCH / 4 + 255) / 256, 256>>>(x, xh, xl, NTOK * CCH);

    // 1) QKV projection
    gemm_bf<<<dim3(C3 / 128, NTOK / 128), 256, SMEM_GEMM>>>(xh, xl, wqh, wql, bqkv, qkvbuf, C3, CCH);

    // 2) causal flash attention
    attn_bf<<<dim3(TT / 64, BB * HH), 128, ATT_SMEM>>>(qkvbuf, attbuf);

    // 3) output projection
    split_bf<<<(NTOK * CCH / 4 + 255) / 256, 256>>>(attbuf, ath, atl, NTOK * CCH);
    gemm_bf<<<dim3(CCH / 128, NTOK / 128), 256, SMEM_GEMM>>>(ath, atl, woh, wol, bo, out, CCH, CCH);
}

// round 14
// speedup vs baseline: 2.0078x; 1.1069x over previous
#include <cuda_runtime.h>
#include <cuda_bf16.h>
#include <cstdint>

// Problem constants
#define BB   2
#define TT   2048
#define CCH  1024
#define HH   16
#define HDIM 64
#define NTOK (BB * TT)     // 4096
#define C3   (3 * CCH)     // 3072

// Scratch (allocation-free rule: __device__ globals)
__device__ float g_qkv[(size_t)NTOK * C3];    // [4096, 3072] fp32
__device__ __nv_bfloat16 g_xh[(size_t)NTOK * CCH];
__device__ __nv_bfloat16 g_xl[(size_t)NTOK * CCH];
__device__ __nv_bfloat16 g_ath[(size_t)NTOK * CCH];   // attn out hi (written by attn_bf)
__device__ __nv_bfloat16 g_atl[(size_t)NTOK * CCH];   // attn out lo
__device__ __nv_bfloat16 g_wqh[(size_t)C3 * CCH];
__device__ __nv_bfloat16 g_wql[(size_t)C3 * CCH];
__device__ __nv_bfloat16 g_woh[(size_t)CCH * CCH];
__device__ __nv_bfloat16 g_wol[(size_t)CCH * CCH];

// ---------------------------------------------------------------------------
// helpers
// ---------------------------------------------------------------------------
__device__ __forceinline__ uint32_t smem_u32(const void* p) {
    uint32_t a;
    asm("{ .reg .u64 t; cvta.to.shared.u64 t, %1; cvt.u32.u64 %0, t; }" : "=r"(a) : "l"(p));
    return a;
}
__device__ __forceinline__ void cp_async16(uint32_t saddr, const void* gaddr) {
    asm volatile("cp.async.ca.shared.global [%0], [%1], 16;" :: "r"(saddr), "l"(gaddr) : "memory");
}
#define CP_COMMIT() asm volatile("cp.async.commit_group;" ::: "memory")
#define CP_WAIT(n)  asm volatile("cp.async.wait_group %0;" :: "n"(n) : "memory")

__device__ __forceinline__ void mma_bf(float* c, const uint32_t* a, const uint32_t* b) {
    asm volatile(
        "mma.sync.aligned.m16n8k16.row.col.f32.bf16.bf16.f32 "
        "{%0,%1,%2,%3}, {%4,%5,%6,%7}, {%8,%9}, {%0,%1,%2,%3};"
        : "+f"(c[0]), "+f"(c[1]), "+f"(c[2]), "+f"(c[3])
        : "r"(a[0]), "r"(a[1]), "r"(a[2]), "r"(a[3]), "r"(b[0]), "r"(b[1]));
}
__device__ __forceinline__ void ldm4(uint32_t& r0, uint32_t& r1, uint32_t& r2, uint32_t& r3,
                                     uint32_t addr) {
    asm volatile("ldmatrix.sync.aligned.m8n8.x4.shared.b16 {%0,%1,%2,%3}, [%4];"
                 : "=r"(r0), "=r"(r1), "=r"(r2), "=r"(r3) : "r"(addr));
}
__device__ __forceinline__ uint32_t pack2(float a, float b) {
    uint32_t r;
    asm("cvt.rn.bf16x2.f32 %0, %1, %2;" : "=r"(r) : "f"(b), "f"(a));
    return r;
}
__device__ __forceinline__ void sp2(float a, float b, uint32_t& whi, uint32_t& wlo) {
    whi = pack2(a, b);
    float ha = __bfloat162float(__float2bfloat16(a));
    float hb = __bfloat162float(__float2bfloat16(b));
    wlo = pack2(a - ha, b - hb);
}
__device__ __forceinline__ float exp2p(float u) {
    u = fmaxf(u, -126.f);
    float z = u + 12582912.f;
    int ki = __float_as_int(z) - 0x4B400000;
    float r = u - (z - 12582912.f);
    float p = 0.00133336f;
    p = fmaf(p, r, 0.00961813f);
    p = fmaf(p, r, 0.05550411f);
    p = fmaf(p, r, 0.24022651f);
    p = fmaf(p, r, 0.69314718f);
    p = fmaf(p, r, 1.0f);
    return __int_as_float(__float_as_int(p) + (ki << 23));
}

// ---------------------------------------------------------------------------
// prep kernels
// ---------------------------------------------------------------------------
__global__ void __launch_bounds__(256) split_bf(
    const float* __restrict__ in, __nv_bfloat16* __restrict__ oh,
    __nv_bfloat16* __restrict__ ol, int n)
{
    const int i = (blockIdx.x * 256 + threadIdx.x) * 4;
    if (i < n) {
        float4 v = *(const float4*)(in + i);
        float vv[4] = { v.x, v.y, v.z, v.w };
#pragma unroll
        for (int j = 0; j < 4; j++) {
            __nv_bfloat16 h = __float2bfloat16(vv[j]);
            oh[i + j] = h;
            ol[i + j] = __float2bfloat16(vv[j] - __bfloat162float(h));
        }
    }
}

__global__ void __launch_bounds__(256) transpose_split_bf(
    const float* __restrict__ in, __nv_bfloat16* __restrict__ oh,
    __nv_bfloat16* __restrict__ ol, int R, int Cc)
{
    __shared__ float t[32][33];
    const int c0 = blockIdx.x * 32, r0 = blockIdx.y * 32;
    const int x = threadIdx.x, y = threadIdx.y;
#pragma unroll
    for (int i = 0; i < 32; i += 8)
        t[y + i][x] = in[(size_t)(r0 + y + i) * Cc + c0 + x];
    __syncthreads();
#pragma unroll
    for (int i = 0; i < 32; i += 8) {
        float v = t[x][y + i];
        __nv_bfloat16 h = __float2bfloat16(v);
        oh[(size_t)(c0 + y + i) * R + r0 + x] = h;
        ol[(size_t)(c0 + y + i) * R + r0 + x] = __float2bfloat16(v - __bfloat162float(h));
    }
}

// ---------------------------------------------------------------------------
// 3-term bf16 GEMM, warp tile 64x64 (4 warps 2m x 2n), CTA 128x128x16.
// ldmatrix fragment loads, 3-stage cp.async pipeline.
// ---------------------------------------------------------------------------
#define PW 12
#define PLANE (128 * PW * 4)             // 6144 B
#define STG (4 * PLANE)                  // 24576 B
#define SMEM_GEMM (3 * STG)              // 73728 B

__global__ void __launch_bounds__(128, 2) gemm_bf(
    const __nv_bfloat16* __restrict__ Ah, const __nv_bfloat16* __restrict__ Al,
    const __nv_bfloat16* __restrict__ Bh, const __nv_bfloat16* __restrict__ Bl,
    const float* __restrict__ bias, float* __restrict__ C,
    int N, int K)
{
    extern __shared__ char smem[];
    const uint32_t sb = smem_u32(smem);

    const int tid = threadIdx.x;
    const int lane = tid & 31;
    const int wid = tid >> 5;                 // 0..3
    const int wm = (wid & 1) * 64;
    const int wn = (wid >> 1) * 64;
    const int g = lane >> 2;
    const int t = lane & 3;

    const int row0 = blockIdx.y * 128;
    const int col0 = blockIdx.x * 128;

    // ldmatrix per-lane base byte offsets within a plane
    const uint32_t aoff = (uint32_t)((wm + (lane & 15)) * PW) * 4 + ((lane >> 4) << 4);
    const uint32_t boff = (uint32_t)((wn + (lane & 7) + ((lane >> 4) << 3)) * PW) * 4
                          + (((lane >> 3) & 1) << 4);

    // loader: 32 threads per plane, 4 rows each
    const int lp = tid >> 5;                  // warp id doubles as plane id
    const int lr = (tid & 31) * 4;
    const __nv_bfloat16* lbase = (lp == 0) ? Ah : (lp == 1) ? Al : (lp == 2) ? Bh : Bl;
    const int lt0 = (lp < 2) ? row0 : col0;

    float c[4][8][4];
#pragma unroll
    for (int mf = 0; mf < 4; mf++)
#pragma unroll
        for (int nf = 0; nf < 8; nf++)
#pragma unroll
            for (int i = 0; i < 4; i++) c[mf][nf][i] = 0.f;

    const int niter = K / 16;

#define LOAD_STAGE(it, s)                                                    \
    {                                                                        \
        const int k0_ = (it) * 16;                                           \
        const __nv_bfloat16* g0 = lbase + (size_t)(lt0 + lr) * K + k0_;      \
        const uint32_t sa = sb + (s) * STG + lp * PLANE + lr * (PW * 4);     \
        _Pragma("unroll")                                                    \
        for (int r = 0; r < 4; r++) {                                        \
            cp_async16(sa + r * (PW * 4), g0 + (size_t)r * K);               \
            cp_async16(sa + r * (PW * 4) + 16, g0 + (size_t)r * K + 8);      \
        }                                                                    \
        CP_COMMIT();                                                         \
    }

    LOAD_STAGE(0, 0);
    LOAD_STAGE(1, 1);
    CP_WAIT(1);
    __syncthreads();

    for (int it = 0; it < niter; it++) {
        const int buf = it % 3;
        const uint32_t sA_h = sb + buf * STG + aoff;
        const uint32_t sA_l = sA_h + PLANE;
        const uint32_t sB_h = sb + buf * STG + 2 * PLANE + boff;
        const uint32_t sB_l = sB_h + PLANE;

        if (it + 2 < niter) LOAD_STAGE(it + 2, (it + 2) % 3);

        // B fragments: 8 nf (2 per ldmatrix.x4), hi + lo planes
        uint32_t bh[8][2], bl[8][2];
#pragma unroll
        for (int np = 0; np < 4; np++) {
            ldm4(bh[2 * np][0], bh[2 * np][1], bh[2 * np + 1][0], bh[2 * np + 1][1],
                 sB_h + np * (16 * PW * 4));
            ldm4(bl[2 * np][0], bl[2 * np][1], bl[2 * np + 1][0], bl[2 * np + 1][1],
                 sB_l + np * (16 * PW * 4));
        }
#pragma unroll
        for (int mf = 0; mf < 4; mf++) {
            uint32_t ah[4], al[4];
            ldm4(ah[0], ah[1], ah[2], ah[3], sA_h + mf * (16 * PW * 4));
            ldm4(al[0], al[1], al[2], al[3], sA_l + mf * (16 * PW * 4));
#pragma unroll
            for (int nf = 0; nf < 8; nf++) {
                mma_bf(c[mf][nf], ah, bl[nf]);
                mma_bf(c[mf][nf], al, bh[nf]);
                mma_bf(c[mf][nf], ah, bh[nf]);
            }
        }

        if (it + 2 < niter) { CP_WAIT(1); } else { CP_WAIT(0); }
        __syncthreads();
    }
#undef LOAD_STAGE

#pragma unroll
    for (int mf = 0; mf < 4; mf++) {
        const int r0_ = row0 + wm + mf * 16 + g;
#pragma unroll
        for (int nf = 0; nf < 8; nf++) {
            const int cc = col0 + wn + nf * 8 + t * 2;
            const float b0 = bias[cc], b1 = bias[cc + 1];
            float2 lo = make_float2(c[mf][nf][0] + b0, c[mf][nf][1] + b1);
            float2 hi = make_float2(c[mf][nf][2] + b0, c[mf][nf][3] + b1);
            *(float2*)&C[(size_t)r0_ * N + cc]       = lo;
            *(float2*)&C[(size_t)(r0_ + 8) * N + cc] = hi;
        }
    }
}

// ---------------------------------------------------------------------------
// 3-term bf16 flash attention (R11 structure), epilogue writes bf16 hi/lo
// planes directly (fused split for the output projection).
// ---------------------------------------------------------------------------
#define AP 36
#define KH_W   0
#define KL_W   2304
#define VTH_W  4608
#define VTL_W  6912
#define PHI_W  9216
#define PLO_W  11520
#define ATT_WORDS 13824
#define ATT_SMEM (ATT_WORDS * 4)         // 55296 B

__global__ void __launch_bounds__(128, 4) attn_bf(
    const float* __restrict__ qkv,
    __nv_bfloat16* __restrict__ oh, __nv_bfloat16* __restrict__ ol)
{
    extern __shared__ uint32_t smw[];
    const uint32_t sb = smem_u32(smw);
    const int tid = threadIdx.x;
    const int lane = tid & 31;
    const int wid = tid >> 5;
    const int g = lane >> 2;
    const int t = lane & 3;

    const int bh_ = blockIdx.y;
    const int b = bh_ >> 4;
    const int h = bh_ & 15;
    const int qtile = (int)gridDim.x - 1 - (int)blockIdx.x;
    const int q0 = qtile * 64;

    const int PHIo = PHI_W + wid * 576;
    const int PLOo = PLO_W + wid * 576;

    const uint32_t bRowOff = (uint32_t)(((lane & 7) + ((lane >> 4) << 3)) * AP) * 4
                             + (((lane >> 3) & 1) << 4);
    const uint32_t kAddr  = sb + KH_W * 4 + bRowOff;
    const uint32_t klAddr = sb + KL_W * 4 + bRowOff;
    const uint32_t vAddr  = sb + VTH_W * 4 + bRowOff;
    const uint32_t vlAddr = sb + VTL_W * 4 + bRowOff;
    const uint32_t pOffA = (uint32_t)((lane & 15) * AP) * 4 + ((lane >> 4) << 4);
    const uint32_t phAddr = sb + PHIo * 4 + pOffA;
    const uint32_t plAddr = sb + PLOo * 4 + pOffA;

    const float QS = 0.125f * 1.44269504f;
    const int grow0 = q0 + wid * 16 + g;
    const int grow1 = grow0 + 8;
    const float* q0p = qkv + (size_t)(b * TT + grow0) * C3 + h * HDIM;
    const float* q1p = q0p + (size_t)8 * C3;

    uint32_t qh[4][4], ql[4][4];
#pragma unroll
    for (int s = 0; s < 4; s++) {
        const int d0 = 2 * (8 * s + t);
        const int d1 = 2 * (8 * s + t + 4);
        sp2(q0p[d0] * QS, q0p[d0 + 1] * QS, qh[s][0], ql[s][0]);
        sp2(q1p[d0] * QS, q1p[d0 + 1] * QS, qh[s][1], ql[s][1]);
        sp2(q0p[d1] * QS, q0p[d1 + 1] * QS, qh[s][2], ql[s][2]);
        sp2(q1p[d1] * QS, q1p[d1 + 1] * QS, qh[s][3], ql[s][3]);
    }

    float o[8][4];
#pragma unroll
    for (int nf = 0; nf < 8; nf++)
#pragma unroll
        for (int i = 0; i < 4; i++) o[nf][i] = 0.f;
    float m0 = -1e30f, m1 = -1e30f, l0 = 0.f, l1 = 0.f;

    const int ntiles = qtile + 1;
    const float* kbase0 = qkv + (size_t)b * TT * C3 + CCH + h * HDIM;

    for (int tile = 0; tile < ntiles; tile++) {
        const int kv0 = tile * 64;
        const float* kb = kbase0 + (size_t)kv0 * C3;

        __syncthreads();

#pragma unroll
        for (int i = 0; i < 8; i++) {
            const int idx = tid + i * 128;
            const int r = idx >> 4, c4 = idx & 15;
            float4 kv4 = *(const float4*)(kb + (size_t)r * C3 + c4 * 4);
            uint32_t h0, l0w, h1, l1w;
            sp2(kv4.x, kv4.y, h0, l0w);
            sp2(kv4.z, kv4.w, h1, l1w);
            const int w = r * AP + c4 * 2;
            smw[KH_W + w] = h0; smw[KH_W + w + 1] = h1;
            smw[KL_W + w] = l0w; smw[KL_W + w + 1] = l1w;
        }
#pragma unroll
        for (int j = 0; j < 2; j++) {
            const int bb2 = tid + j * 128;
            const int br = (bb2 >> 4) * 4;
            const int bc = (bb2 & 15) * 4;
            const float* vb = kb + CCH;
            float4 v0 = *(const float4*)(vb + (size_t)(br + 0) * C3 + bc);
            float4 v1 = *(const float4*)(vb + (size_t)(br + 1) * C3 + bc);
            float4 v2 = *(const float4*)(vb + (size_t)(br + 2) * C3 + bc);
            float4 v3 = *(const float4*)(vb + (size_t)(br + 3) * C3 + bc);
            float4 rowv[4] = {
                make_float4(v0.x, v1.x, v2.x, v3.x),
                make_float4(v0.y, v1.y, v2.y, v3.y),
                make_float4(v0.z, v1.z, v2.z, v3.z),
                make_float4(v0.w, v1.w, v2.w, v3.w)
            };
#pragma unroll
            for (int d = 0; d < 4; d++) {
                uint32_t h0, l0w, h1, l1w;
                sp2(rowv[d].x, rowv[d].y, h0, l0w);
                sp2(rowv[d].z, rowv[d].w, h1, l1w);
                const int w = (bc + d) * AP + (br >> 1);
                smw[VTH_W + w] = h0; smw[VTH_W + w + 1] = h1;
                smw[VTL_W + w] = l0w; smw[VTL_W + w + 1] = l1w;
            }
        }
        __syncthreads();

        float s[8][4];
#pragma unroll
        for (int nf = 0; nf < 8; nf++)
#pragma unroll
            for (int i = 0; i < 4; i++) s[nf][i] = 0.f;
#pragma unroll
        for (int sl = 0; sl < 4; sl++) {
            const uint32_t slo = sl * 32;
#pragma unroll
            for (int np = 0; np < 4; np++) {
                uint32_t kh0, kh1, kh2w, kh3, kl0, kl1, kl2w, kl3;
                ldm4(kh0, kh1, kh2w, kh3, kAddr + np * (16 * AP * 4) + slo);
                ldm4(kl0, kl1, kl2w, kl3, klAddr + np * (16 * AP * 4) + slo);
                uint32_t bh0[2] = { kh0, kh1 }, bh1[2] = { kh2w, kh3 };
                uint32_t bl0[2] = { kl0, kl1 }, bl1[2] = { kl2w, kl3 };
                mma_bf(s[2 * np],     qh[sl], bl0);
                mma_bf(s[2 * np],     ql[sl], bh0);
                mma_bf(s[2 * np],     qh[sl], bh0);
                mma_bf(s[2 * np + 1], qh[sl], bl1);
                mma_bf(s[2 * np + 1], ql[sl], bh1);
                mma_bf(s[2 * np + 1], qh[sl], bh1);
            }
        }

        if (tile == qtile) {
#pragma unroll
            for (int nf = 0; nf < 8; nf++) {
                const int c0 = kv0 + nf * 8 + 2 * t;
                if (c0 > grow0)     s[nf][0] = -1e30f;
                if (c0 + 1 > grow0) s[nf][1] = -1e30f;
                if (c0 > grow1)     s[nf][2] = -1e30f;
                if (c0 + 1 > grow1) s[nf][3] = -1e30f;
            }
        }

        float tm0 = -1e30f, tm1 = -1e30f;
#pragma unroll
        for (int nf = 0; nf < 8; nf++) {
            tm0 = fmaxf(tm0, fmaxf(s[nf][0], s[nf][1]));
            tm1 = fmaxf(tm1, fmaxf(s[nf][2], s[nf][3]));
        }
        tm0 = fmaxf(tm0, __shfl_xor_sync(0xffffffffu, tm0, 1));
        tm0 = fmaxf(tm0, __shfl_xor_sync(0xffffffffu, tm0, 2));
        tm1 = fmaxf(tm1, __shfl_xor_sync(0xffffffffu, tm1, 1));
        tm1 = fmaxf(tm1, __shfl_xor_sync(0xffffffffu, tm1, 2));
        const float mn0 = fmaxf(m0, tm0);
        const float mn1 = fmaxf(m1, tm1);
        const float cr0 = exp2p(m0 - mn0);
        const float cr1 = exp2p(m1 - mn1);
        m0 = mn0; m1 = mn1;
        l0 *= cr0; l1 *= cr1;
#pragma unroll
        for (int nf = 0; nf < 8; nf++) {
            o[nf][0] *= cr0; o[nf][1] *= cr0;
            o[nf][2] *= cr1; o[nf][3] *= cr1;
        }

#pragma unroll
        for (int nf = 0; nf < 8; nf++) {
            const float p0 = exp2p(s[nf][0] - m0);
            const float p1 = exp2p(s[nf][1] - m0);
            const float p2 = exp2p(s[nf][2] - m1);
            const float p3 = exp2p(s[nf][3] - m1);
            l0 += p0 + p1;
            l1 += p2 + p3;
            uint32_t w0h, w0l, w1h, w1l;
            sp2(p0, p1, w0h, w0l);
            sp2(p2, p3, w1h, w1l);
            const int w = 4 * nf + t;
            smw[PHIo + g * AP + w] = w0h;
            smw[PLOo + g * AP + w] = w0l;
            smw[PHIo + (g + 8) * AP + w] = w1h;
            smw[PLOo + (g + 8) * AP + w] = w1l;
        }
        __syncwarp();

#pragma unroll
        for (int sl = 0; sl < 4; sl++) {
            const uint32_t slo = sl * 32;
            uint32_t ph[4], pl[4];
            ldm4(ph[0], ph[1], ph[2], ph[3], phAddr + slo);
            ldm4(pl[0], pl[1], pl[2], pl[3], plAddr + slo);
#pragma unroll
            for (int np = 0; np < 4; np++) {
                uint32_t vh0, vh1, vh2w, vh3, vl0, vl1, vl2w, vl3;
                ldm4(vh0, vh1, vh2w, vh3, vAddr + np * (16 * AP * 4) + slo);
                ldm4(vl0, vl1, vl2w, vl3, vlAddr + np * (16 * AP * 4) + slo);
                uint32_t bh0[2] = { vh0, vh1 }, bh1[2] = { vh2w, vh3 };
                uint32_t bl0[2] = { vl0, vl1 }, bl1[2] = { vl2w, vl3 };
                mma_bf(o[2 * np],     ph, bl0);
                mma_bf(o[2 * np],     pl, bh0);
                mma_bf(o[2 * np],     ph, bh0);
                mma_bf(o[2 * np + 1], ph, bl1);
                mma_bf(o[2 * np + 1], pl, bh1);
                mma_bf(o[2 * np + 1], ph, bh1);
            }
        }
        __syncwarp();
    }

    l0 += __shfl_xor_sync(0xffffffffu, l0, 1);
    l0 += __shfl_xor_sync(0xffffffffu, l0, 2);
    l1 += __shfl_xor_sync(0xffffffffu, l1, 1);
    l1 += __shfl_xor_sync(0xffffffffu, l1, 2);
    const float inv0 = 1.f / l0;
    const float inv1 = 1.f / l1;

    // fused epilogue: write bf16 hi/lo planes directly
    const size_t ob0 = (size_t)(b * TT + grow0) * CCH + h * HDIM;
    const size_t ob1 = (size_t)(b * TT + grow1) * CCH + h * HDIM;
#pragma unroll
    for (int nf = 0; nf < 8; nf++) {
        const int cidx = nf * 8 + 2 * t;
        uint32_t wh, wl;
        sp2(o[nf][0] * inv0, o[nf][1] * inv0, wh, wl);
        *(uint32_t*)&oh[ob0 + cidx] = wh;
        *(uint32_t*)&ol[ob0 + cidx] = wl;
        sp2(o[nf][2] * inv1, o[nf][3] * inv1, wh, wl);
        *(uint32_t*)&oh[ob1 + cidx] = wh;
        *(uint32_t*)&ol[ob1 + cidx] = wl;
    }
}

// ---------------------------------------------------------------------------
extern "C" void kernel_launch(void* const* d_in, const int* in_sizes, int n_in,
                              void* d_out, int out_size)
{
    (void)in_sizes; (void)n_in; (void)out_size;
    const float* x    = (const float*)d_in[0];
    const float* Wqkv = (const float*)d_in[1];
    const float* bqkv = (const float*)d_in[2];
    const float* Wo   = (const float*)d_in[3];
    const float* bo   = (const float*)d_in[4];
    float* out = (float*)d_out;

    float *qkvbuf;
    __nv_bfloat16 *xh, *xl, *ath, *atl, *wqh, *wql, *woh, *wol;
    cudaGetSymbolAddress((void**)&qkvbuf, g_qkv);
    cudaGetSymbolAddress((void**)&xh,  g_xh);
    cudaGetSymbolAddress((void**)&xl,  g_xl);
    cudaGetSymbolAddress((void**)&ath, g_ath);
    cudaGetSymbolAddress((void**)&atl, g_atl);
    cudaGetSymbolAddress((void**)&wqh, g_wqh);
    cudaGetSymbolAddress((void**)&wql, g_wql);
    cudaGetSymbolAddress((void**)&woh, g_woh);
    cudaGetSymbolAddress((void**)&wol, g_wol);

    static int smem_set = 0;
    if (!smem_set) {
        cudaFuncSetAttribute(gemm_bf, cudaFuncAttributeMaxDynamicSharedMemorySize, SMEM_GEMM);
        cudaFuncSetAttribute(attn_bf, cudaFuncAttributeMaxDynamicSharedMemorySize, ATT_SMEM);
        smem_set = 1;
    }

    // 0) prep
    transpose_split_bf<<<dim3(C3 / 32, CCH / 32), dim3(32, 8)>>>(Wqkv, wqh, wql, CCH, C3);
    transpose_split_bf<<<dim3(CCH / 32, CCH / 32), dim3(32, 8)>>>(Wo, woh, wol, CCH, CCH);
    split_bf<<<(NTOK * CCH / 4 + 255) / 256, 256>>>(x, xh, xl, NTOK * CCH);

    // 1) QKV projection (warp tile 64x64)
    gemm_bf<<<dim3(C3 / 128, NTOK / 128), 128, SMEM_GEMM>>>(xh, xl, wqh, wql, bqkv, qkvbuf, C3, CCH);

    // 2) causal flash attention (writes bf16 hi/lo planes)
    attn_bf<<<dim3(TT / 64, BB * HH), 128, ATT_SMEM>>>(qkvbuf, ath, atl);

    // 3) output projection
    gemm_bf<<<dim3(CCH / 128, NTOK / 128), 128, SMEM_GEMM>>>(ath, atl, woh, wol, bo, out, CCH, CCH);
}